// round 1
// baseline (speedup 1.0000x reference)
#include <cuda_runtime.h>
#include <math.h>

#define BB 64
#define TT 512
#define EE 256
#define HH 512
#define G4 2048            // 4*H
#define NB 128             // persistent scan blocks (<=148, one wave)
#define JPB 4              // hidden units per block = HH/NB

#define OUT_HT_OFF  16777216ull           // B*T*H
#define OUT_CT_OFF  16809984ull           // + B*H
#define OUT_MASK_OFF 16842752ull          // + B*H

// -------- device scratch (no allocations allowed) --------
__device__ float g_gates[(size_t)TT * G4 * BB];   // 256 MB: [t][g][b]
__device__ float g_hbuf[2][HH * BB];              // double-buffered h, layout [k][b]
__device__ unsigned g_bar_count;
__device__ unsigned g_bar_phase;

// -------- reset kernel: barrier state + h0 = 0 (run each launch for graph replay determinism) --------
__global__ void reset_kernel() {
    int idx = blockIdx.x * blockDim.x + threadIdx.x;
    if (idx == 0) { g_bar_count = 0u; g_bar_phase = 0u; }
    if (idx < HH * BB) {
        g_hbuf[0][idx] = 0.f;
        g_hbuf[1][idx] = 0.f;
    }
}

// -------- mask kernel --------
__global__ void mask_kernel(const int* __restrict__ lengths, float* __restrict__ out_mask) {
    int t = threadIdx.x;
    int b = blockIdx.x;
    out_mask[(size_t)b * TT + t] = (t < lengths[b]) ? 1.0f : 0.0f;
}

// -------- gates_x GEMM: G[t][g][b] = sum_e emb[inputs[b][t]][e] * W_ih[g][e] + b_ih[g] + b_hh[g] --------
// grid: (32 g-tiles, 512 t), block 256 threads, tile 64g x 64b, K-chunks of 32.
__global__ __launch_bounds__(256) void gates_kernel(
    const int* __restrict__ inputs, const float* __restrict__ emb,
    const float* __restrict__ W_ih, const float* __restrict__ b_ih,
    const float* __restrict__ b_hh)
{
    __shared__ float xs[BB][33];     // [b][kk], pad 33 -> conflict-free stores
    __shared__ float Ws[32][68];     // [kk][g], pad 68 -> aligned float4 reads
    __shared__ int   ts[BB];

    const int t  = blockIdx.y;
    const int g0 = blockIdx.x * 64;
    const int tid = threadIdx.x;

    if (tid < BB) ts[tid] = inputs[(size_t)tid * TT + t];
    __syncthreads();

    const int bq = tid & 15;        // 16 batch groups (4 b each)
    const int gq = tid >> 4;        // 16 gate groups (4 g each)
    const int lk = tid & 31;        // loader: kk lane
    const int ls = tid >> 5;        // loader: row sub (8 rows/pass)

    float acc[4][4];
#pragma unroll
    for (int i = 0; i < 4; i++)
#pragma unroll
        for (int jj = 0; jj < 4; jj++) acc[i][jj] = 0.f;

    for (int kc = 0; kc < EE; kc += 32) {
        // load x tile (gather from emb), coalesced over kk
#pragma unroll
        for (int bp = 0; bp < 8; bp++) {
            int b = ls + bp * 8;
            xs[b][lk] = emb[(size_t)ts[b] * EE + kc + lk];
        }
        // load W tile, coalesced over kk
#pragma unroll
        for (int gp = 0; gp < 8; gp++) {
            int g = ls + gp * 8;
            Ws[lk][g] = W_ih[(size_t)(g0 + g) * EE + kc + lk];
        }
        __syncthreads();

#pragma unroll
        for (int kk = 0; kk < 32; kk++) {
            float x0 = xs[4 * bq + 0][kk];
            float x1 = xs[4 * bq + 1][kk];
            float x2 = xs[4 * bq + 2][kk];
            float x3 = xs[4 * bq + 3][kk];
            float4 w = *(const float4*)&Ws[kk][4 * gq];
            acc[0][0] = fmaf(w.x, x0, acc[0][0]);
            acc[0][1] = fmaf(w.x, x1, acc[0][1]);
            acc[0][2] = fmaf(w.x, x2, acc[0][2]);
            acc[0][3] = fmaf(w.x, x3, acc[0][3]);
            acc[1][0] = fmaf(w.y, x0, acc[1][0]);
            acc[1][1] = fmaf(w.y, x1, acc[1][1]);
            acc[1][2] = fmaf(w.y, x2, acc[1][2]);
            acc[1][3] = fmaf(w.y, x3, acc[1][3]);
            acc[2][0] = fmaf(w.z, x0, acc[2][0]);
            acc[2][1] = fmaf(w.z, x1, acc[2][1]);
            acc[2][2] = fmaf(w.z, x2, acc[2][2]);
            acc[2][3] = fmaf(w.z, x3, acc[2][3]);
            acc[3][0] = fmaf(w.w, x0, acc[3][0]);
            acc[3][1] = fmaf(w.w, x1, acc[3][1]);
            acc[3][2] = fmaf(w.w, x2, acc[3][2]);
            acc[3][3] = fmaf(w.w, x3, acc[3][3]);
        }
        __syncthreads();
    }

    const size_t tbase = (size_t)t * (G4 * BB);
#pragma unroll
    for (int gi = 0; gi < 4; gi++) {
        int g = g0 + 4 * gq + gi;
        float bias = b_ih[g] + b_hh[g];
        size_t base = tbase + (size_t)g * BB + 4 * bq;
#pragma unroll
        for (int bi = 0; bi < 4; bi++) {
            g_gates[base + bi] = acc[gi][bi] + bias;
        }
    }
}

// -------- grid-wide barrier (all NB blocks resident by construction) --------
__device__ __forceinline__ void grid_barrier(unsigned target, unsigned nb) {
    __syncthreads();
    if (threadIdx.x == 0) {
        __threadfence();
        unsigned prev = atomicAdd(&g_bar_count, 1u);
        if (prev == nb - 1u) {
            atomicExch(&g_bar_count, 0u);
            __threadfence();
            atomicExch(&g_bar_phase, target);
        } else {
            while (*((volatile unsigned*)&g_bar_phase) < target) { }
            __threadfence();
        }
    }
    __syncthreads();
}

__device__ __forceinline__ float sigmoidf_(float x) {
    return 1.0f / (1.0f + __expf(-x));
}

// -------- persistent LSTM scan --------
// 128 blocks x 256 threads. Block owns JPB=4 hidden units for all 64 batches.
// Thread (jl, b) owns cell state c[b][j0+jl] in registers across all 512 steps.
__global__ __launch_bounds__(256, 1) void scan_kernel(
    const int* __restrict__ lengths, const int* __restrict__ reset_idx,
    const float* __restrict__ W_hh, float* __restrict__ out)
{
    extern __shared__ float sm[];
    float* h_s = sm;                 // [HH][BB] = 32768 floats
    float* Wsl = sm + HH * BB;       // [16][HH] = 8192 floats

    const int tid = threadIdx.x;
    const int jl  = tid >> 6;        // 0..3
    const int b   = tid & 63;
    const int j0  = blockIdx.x * JPB;
    const int j   = j0 + jl;

    // Preload this block's W_hh slice: rows gate*H + (j0+jj), 16 rows x 512
    for (int i = tid; i < 16 * HH; i += 256) {
        int r = i >> 9;              // 0..15
        int k = i & (HH - 1);
        int gate = r >> 2, jj = r & 3;
        Wsl[i] = W_hh[(size_t)(gate * HH + j0 + jj) * HH + k];
    }

    float hprev = 0.f, cprev = 0.f;
    const int len = lengths[b];
    __syncthreads();

    const float* Wi = Wsl + (0 * 4 + jl) * HH;
    const float* Wf = Wsl + (1 * 4 + jl) * HH;
    const float* Wg = Wsl + (2 * 4 + jl) * HH;
    const float* Wo = Wsl + (3 * 4 + jl) * HH;

    for (int t = 0; t < TT; t++) {
        // independent global loads first (latency overlap with h copy)
        const size_t gbase = (size_t)t * (G4 * BB);
        float a_i = g_gates[gbase + (size_t)(0 * HH + j) * BB + b];
        float a_f = g_gates[gbase + (size_t)(1 * HH + j) * BB + b];
        float a_g = g_gates[gbase + (size_t)(2 * HH + j) * BB + b];
        float a_o = g_gates[gbase + (size_t)(3 * HH + j) * BB + b];
        const int rv = reset_idx[(size_t)b * TT + t];

        // copy h (prev step) into shared, [k][b] layout
        {
            const float4* src = (const float4*)g_hbuf[t & 1];
            float4* dst = (float4*)h_s;
#pragma unroll
            for (int i = 0; i < 32; i++) {
                dst[tid + i * 256] = src[tid + i * 256];
            }
        }
        __syncthreads();

        // 4 dots of length 512 over h
#pragma unroll 2
        for (int k = 0; k < HH; k += 4) {
            float h0 = h_s[(k + 0) * BB + b];
            float h1 = h_s[(k + 1) * BB + b];
            float h2 = h_s[(k + 2) * BB + b];
            float h3 = h_s[(k + 3) * BB + b];
            float4 wi = *(const float4*)(Wi + k);
            float4 wf = *(const float4*)(Wf + k);
            float4 wg = *(const float4*)(Wg + k);
            float4 wo = *(const float4*)(Wo + k);
            a_i = fmaf(h0, wi.x, a_i); a_i = fmaf(h1, wi.y, a_i);
            a_i = fmaf(h2, wi.z, a_i); a_i = fmaf(h3, wi.w, a_i);
            a_f = fmaf(h0, wf.x, a_f); a_f = fmaf(h1, wf.y, a_f);
            a_f = fmaf(h2, wf.z, a_f); a_f = fmaf(h3, wf.w, a_f);
            a_g = fmaf(h0, wg.x, a_g); a_g = fmaf(h1, wg.y, a_g);
            a_g = fmaf(h2, wg.z, a_g); a_g = fmaf(h3, wg.w, a_g);
            a_o = fmaf(h0, wo.x, a_o); a_o = fmaf(h1, wo.y, a_o);
            a_o = fmaf(h2, wo.z, a_o); a_o = fmaf(h3, wo.w, a_o);
        }

        // LSTM cell
        float ig = sigmoidf_(a_i);
        float fg = sigmoidf_(a_f);
        float gg = tanhf(a_g);
        float og = sigmoidf_(a_o);
        float c_new = fmaf(fg, cprev, ig * gg);
        float h_new = og * tanhf(c_new);

        bool m = (t < len);
        float h_next = m ? h_new : hprev;
        float c_next = m ? c_new : cprev;

        out[(size_t)b * (TT * HH) + (size_t)t * HH + j] = h_next;

        hprev = rv ? 0.f : h_next;
        cprev = rv ? 0.f : c_next;

        g_hbuf[(t + 1) & 1][(size_t)j * BB + b] = hprev;

        if (t == TT - 1) {
            out[OUT_HT_OFF + (size_t)b * HH + j] = hprev;
            out[OUT_CT_OFF + (size_t)b * HH + j] = cprev;
        } else {
            grid_barrier((unsigned)(t + 1), (unsigned)gridDim.x);
        }
    }
}

extern "C" void kernel_launch(void* const* d_in, const int* in_sizes, int n_in,
                              void* d_out, int out_size) {
    const int*   inputs    = (const int*)d_in[0];
    const int*   lengths   = (const int*)d_in[1];
    const int*   reset_idx = (const int*)d_in[2];
    const float* emb       = (const float*)d_in[3];
    const float* W_ih      = (const float*)d_in[4];
    const float* W_hh      = (const float*)d_in[5];
    const float* b_ih      = (const float*)d_in[6];
    const float* b_hh      = (const float*)d_in[7];
    float* out = (float*)d_out;

    const int smem_scan = (HH * BB + 16 * HH) * (int)sizeof(float);  // 163840 B
    cudaFuncSetAttribute(scan_kernel, cudaFuncAttributeMaxDynamicSharedMemorySize, smem_scan);

    reset_kernel<<<128, 256>>>();
    gates_kernel<<<dim3(32, 512), 256>>>(inputs, emb, W_ih, b_ih, b_hh);
    mask_kernel<<<BB, TT>>>(lengths, out + OUT_MASK_OFF);
    scan_kernel<<<NB, 256, smem_scan>>>(lengths, reset_idx, W_hh, out);
}